// round 2
// baseline (speedup 1.0000x reference)
#include <cuda_runtime.h>

// DAG fused 1x1-conv layer, fp32, packed f32x2 FMA, smem-resident weights.
// B=64, C=64, HW=1024. 16 GEMMs of [64pos x 64 x 64] per block tile.
//
// One block = (batch, 64-position tile), 512 threads (16 warps -> 4/SMSP).
// All 6 DAG states live in smem (ReLU'd form; raw node values go straight
// to global from registers). Weights are transposed to [g][c][o] once in
// global scratch, then staged per-GEMM into smem double buffers, splatted
// to {w,w} pairs at STS time so the inner loop is pure fma.rn.f32x2:
//   per c-iter/thread: 1 LDS.128 (x: 4 pos), 1 LDS.128 (w: 2 splat pairs),
//   4 FFMA2 -> 16 flops. No LDG, no movs, no relu in the loop.

#define NG        16
#define TPOS      64
#define NTHREADS  512
#define SMEM_FLOATS (6 * 4096 + 2 * 8192)      // states + 2 weight buffers
#define SMEM_BYTES  (SMEM_FLOATS * 4)          // 163840 B = 160 KB

// [g][c][o] transposed weights, 16 * 4096 floats = 256 KB scratch
__device__ __align__(16) float g_wsp[NG * 64 * 64];

__global__ void prep_weights_kernel(const float* __restrict__ Wpre,
                                    const float* __restrict__ Wedge) {
    int idx = blockIdx.x * blockDim.x + threadIdx.x;
    if (idx >= NG * 4096) return;
    int g = idx >> 12;
    int r = idx & 4095;
    int o = r >> 6;
    int c = r & 63;
    float w = (g < 2) ? Wpre[g * 4096 + o * 64 + c]
                      : Wedge[(g - 2) * 4096 + o * 64 + c];
    g_wsp[(g * 64 + c) * 64 + o] = w;
}

__device__ __forceinline__ void ffma2(unsigned long long& d,
                                      unsigned long long a,
                                      unsigned long long b) {
    asm("fma.rn.f32x2 %0, %1, %2, %0;" : "+l"(d) : "l"(a), "l"(b));
}

__device__ __forceinline__ float2 u2f2(unsigned long long v) {
    float2 r;
    asm("mov.b64 {%0, %1}, %2;" : "=f"(r.x), "=f"(r.y) : "l"(v));
    return r;
}

__global__ void __launch_bounds__(NTHREADS, 1)
dag_kernel(const float* __restrict__ x0,
           const float* __restrict__ x1,
           float* __restrict__ out) {
    extern __shared__ float sm[];
    float* st = sm;                   // 6 state slots x [64 c][64 p]
    float* wb = sm + 6 * 4096;        // 2 weight buffers x [64 c][128] (splatted)

    const int tid = threadIdx.x;
    const int b   = blockIdx.x >> 4;
    const int p0  = (blockIdx.x & 15) * TPOS;

    // --- Stage raw x0 -> slot 4, x1 -> slot 5 (overwritten by nodes 2,3 later)
    {
        const float4* gx0 = reinterpret_cast<const float4*>(x0 + b * 65536 + p0);
        const float4* gx1 = reinterpret_cast<const float4*>(x1 + b * 65536 + p0);
        float4* s4 = reinterpret_cast<float4*>(st + 4 * 4096);
        float4* s5 = reinterpret_cast<float4*>(st + 5 * 4096);
        #pragma unroll
        for (int j = 0; j < 2; ++j) {
            int id = tid + j * NTHREADS;   // 0..1023 float4s = 64 c x 16 q
            int c = id >> 4;
            int q = id & 15;
            s4[c * 16 + q] = gx0[c * 256 + q];
            s5[c * 16 + q] = gx1[c * 256 + q];
        }
    }

    // --- Weight staging: thread owns 8 consecutive floats of one [c] row
    const int wt_c = tid >> 3;           // 0..63
    const int wt_o = (tid & 7) * 8;      // 0..56
    float4 wr0, wr1;

    // prologue: load w0, splat-store into buf0; prefetch w1 into regs
    {
        const float4* src = reinterpret_cast<const float4*>(g_wsp + tid * 8);
        wr0 = src[0]; wr1 = src[1];
        float* d = wb + wt_c * 128 + wt_o * 2;
        reinterpret_cast<float4*>(d)[0] = make_float4(wr0.x, wr0.x, wr0.y, wr0.y);
        reinterpret_cast<float4*>(d)[1] = make_float4(wr0.z, wr0.z, wr0.w, wr0.w);
        reinterpret_cast<float4*>(d)[2] = make_float4(wr1.x, wr1.x, wr1.y, wr1.y);
        reinterpret_cast<float4*>(d)[3] = make_float4(wr1.z, wr1.z, wr1.w, wr1.w);
        const float4* src1 = reinterpret_cast<const float4*>(g_wsp + 4096 + tid * 8);
        wr0 = src1[0]; wr1 = src1[1];
    }
    __syncthreads();

    // --- Thread compute tile: 2 output channels x 4 positions
    const int o0 = (tid >> 4) * 2;    // 0..62
    const int p  = (tid & 15) * 4;    // 0..60

    unsigned long long A[2][2];       // [o][pos-pair]

    // GEMM schedule: g0,g1 = preproc; then nodes 0..3 summing prior states.
    constexpr int IN[NG]   = {4,5, 0,1, 0,1,2, 0,1,2,3, 0,1,2,3,4};
    constexpr int STRT[NG] = {1,1, 1,0, 1,0,0, 1,0,0,0, 1,0,0,0,0};
    constexpr int OUTS[NG] = {0,1, -1,2, -1,-1,3, -1,-1,-1,4, -1,-1,-1,-1,5};
    constexpr int NODE[NG] = {-1,-1, -1,0, -1,-1,1, -1,-1,-1,2, -1,-1,-1,-1,3};

    #pragma unroll
    for (int g = 0; g < NG; ++g) {
        if (STRT[g]) {
            A[0][0] = 0ull; A[0][1] = 0ull; A[1][0] = 0ull; A[1][1] = 0ull;
        }
        // --- GEMM: acc += W[g] * relu_state[IN[g]]
        {
            const float* xp = st + IN[g] * 4096 + p;
            const float* wp = wb + (g & 1) * 8192 + o0 * 2;
            #pragma unroll 8
            for (int c = 0; c < 64; ++c) {
                ulonglong2 xv = *reinterpret_cast<const ulonglong2*>(xp);
                ulonglong2 wv = *reinterpret_cast<const ulonglong2*>(wp);
                ffma2(A[0][0], wv.x, xv.x); ffma2(A[0][1], wv.x, xv.y);
                ffma2(A[1][0], wv.y, xv.x); ffma2(A[1][1], wv.y, xv.y);
                xp += TPOS;
                wp += 128;
            }
        }
        // --- Completed state: raw -> global (nodes), ReLU'd -> smem
        if (OUTS[g] >= 0) {
            float* sd = st + OUTS[g] * 4096;
            #pragma unroll
            for (int oo = 0; oo < 2; ++oo) {
                float2 a = u2f2(A[oo][0]);
                float2 c2 = u2f2(A[oo][1]);
                if (NODE[g] >= 0) {
                    *reinterpret_cast<float4*>(
                        out + b * 262144 + NODE[g] * 65536 + (o0 + oo) * 1024 + p0 + p)
                        = make_float4(a.x, a.y, c2.x, c2.y);
                }
                *reinterpret_cast<float4*>(sd + (o0 + oo) * TPOS + p) =
                    make_float4(fmaxf(a.x, 0.f), fmaxf(a.y, 0.f),
                                fmaxf(c2.x, 0.f), fmaxf(c2.y, 0.f));
            }
        }
        // --- Stage weights: STS w[g+1] (held in regs), prefetch LDG w[g+2]
        if (g + 1 < NG) {
            float* d = wb + ((g + 1) & 1) * 8192 + wt_c * 128 + wt_o * 2;
            reinterpret_cast<float4*>(d)[0] = make_float4(wr0.x, wr0.x, wr0.y, wr0.y);
            reinterpret_cast<float4*>(d)[1] = make_float4(wr0.z, wr0.z, wr0.w, wr0.w);
            reinterpret_cast<float4*>(d)[2] = make_float4(wr1.x, wr1.x, wr1.y, wr1.y);
            reinterpret_cast<float4*>(d)[3] = make_float4(wr1.z, wr1.z, wr1.w, wr1.w);
        }
        if (g + 2 < NG) {
            const float4* src =
                reinterpret_cast<const float4*>(g_wsp + (g + 2) * 4096 + tid * 8);
            wr0 = src[0]; wr1 = src[1];
        }
        __syncthreads();
    }
}

extern "C" void kernel_launch(void* const* d_in, const int* in_sizes, int n_in,
                              void* d_out, int out_size) {
    const float* x0    = (const float*)d_in[0];
    const float* x1    = (const float*)d_in[1];
    const float* Wpre  = (const float*)d_in[2];
    const float* Wedge = (const float*)d_in[3];
    float* out = (float*)d_out;

    prep_weights_kernel<<<256, 256>>>(Wpre, Wedge);

    cudaFuncSetAttribute(dag_kernel,
                         cudaFuncAttributeMaxDynamicSharedMemorySize,
                         SMEM_BYTES);
    dag_kernel<<<64 * 16, NTHREADS, SMEM_BYTES>>>(x0, x1, out);
}

// round 4
// speedup vs baseline: 2.0711x; 2.0711x over previous
#include <cuda_runtime.h>

// DAG fused 1x1-conv, fp32, f32x2 FMA, crossbar-balanced 8x8 thread tile.
// Block = (batch, 128-position tile), 128 threads. 6 states resident in
// smem (relu'd; raw node values go to global from regs). Weights [g][c][o]
// in global scratch, double-buffered into smem UNSPLATTED (16 B/thread/c);
// {w,w} pairs built with mov.b64 on the idle ALU pipe. Inner c-iter/thread:
// 2 LDS.128 (x) + 2 LDS.128 (w) + 8 packs + 32 FFMA2.
// Per SM per c-iter: LDS crossbar 32 cyc vs FMA 64 cyc -> FMA-bound.

#define NG        16
#define NTHREADS  128
#define SLOT      8192                       // floats per state slot (64 c x 128 p)
#define SMEM_FLOATS (6 * SLOT + 2 * 4096)    // states + 2 weight buffers
#define SMEM_BYTES  (SMEM_FLOATS * 4)        // 229376 B

// GEMM schedule in constant memory (reviewable; LDC once per GEMM iter).
// g0,g1 = preproc convs; then node i sums convs of all prior states.
__constant__ int c_in[NG]    = {4,5, 0,1, 0,1,2, 0,1,2,3, 0,1,2,3,4};
__constant__ int c_start[NG] = {1,1, 1,0, 1,0,0, 1,0,0,0, 1,0,0,0,0};
__constant__ int c_fin[NG]   = {1,1, 0,1, 0,0,1, 0,0,0,1, 0,0,0,0,1};

// [g][c][o] transposed weights, 16 * 4096 floats
__device__ __align__(16) float g_wsp[NG * 4096];

__global__ void prep_weights_kernel(const float* __restrict__ Wpre,
                                    const float* __restrict__ Wedge) {
    int idx = blockIdx.x * blockDim.x + threadIdx.x;
    if (idx >= NG * 4096) return;
    int g = idx >> 12;
    int r = idx & 4095;
    int o = r >> 6;
    int c = r & 63;
    float w = (g < 2) ? Wpre[g * 4096 + o * 64 + c]
                      : Wedge[(g - 2) * 4096 + o * 64 + c];
    g_wsp[(g * 64 + c) * 64 + o] = w;
}

__device__ __forceinline__ void ffma2(unsigned long long& d,
                                      unsigned long long a,
                                      unsigned long long b) {
    asm("fma.rn.f32x2 %0, %1, %2, %0;" : "+l"(d) : "l"(a), "l"(b));
}
__device__ __forceinline__ unsigned long long splat2(float w) {
    unsigned long long r;
    asm("mov.b64 %0, {%1, %1};" : "=l"(r) : "f"(w));
    return r;
}
__device__ __forceinline__ float2 u2f2(unsigned long long v) {
    float2 r;
    asm("mov.b64 {%0, %1}, %2;" : "=f"(r.x), "=f"(r.y) : "l"(v));
    return r;
}

__global__ void __launch_bounds__(NTHREADS, 1)
dag_kernel(const float* __restrict__ x0,
           const float* __restrict__ x1,
           float* __restrict__ out) {
    extern __shared__ __align__(16) float sm[];
    float* st = sm;                 // 6 state slots [64 c][128 p]
    float* wb = sm + 6 * SLOT;      // 2 weight buffers [64 c][64 o]

    const int tid = threadIdx.x;
    const int b   = blockIdx.x >> 3;
    const int p0  = (blockIdx.x & 7) * 128;

    // --- Stage raw x0 -> slot 4, x1 -> slot 5 (consumed only by g0,g1;
    //     later overwritten by node2/node3 states)
    {
        const float4* gx0 = reinterpret_cast<const float4*>(x0 + b * 65536 + p0);
        const float4* gx1 = reinterpret_cast<const float4*>(x1 + b * 65536 + p0);
        float4* s4 = reinterpret_cast<float4*>(st + 4 * SLOT);
        float4* s5 = reinterpret_cast<float4*>(st + 5 * SLOT);
        #pragma unroll
        for (int j = 0; j < 16; ++j) {
            int id = tid + j * NTHREADS;     // 0..2047 float4s = [64 c][32 q]
            int c = id >> 5;
            int q = id & 31;
            s4[id] = gx0[c * 256 + q];
            s5[id] = gx1[c * 256 + q];
        }
    }

    // --- Weight prologue: w0 -> buf0 ; w1 prefetched into regs
    float4 wr[8];
    {
        const float4* s0 = reinterpret_cast<const float4*>(g_wsp);
        #pragma unroll
        for (int j = 0; j < 8; ++j) wr[j] = s0[tid + j * NTHREADS];
        float4* d0 = reinterpret_cast<float4*>(wb);
        #pragma unroll
        for (int j = 0; j < 8; ++j) d0[tid + j * NTHREADS] = wr[j];
        const float4* s1 = reinterpret_cast<const float4*>(g_wsp + 4096);
        #pragma unroll
        for (int j = 0; j < 8; ++j) wr[j] = s1[tid + j * NTHREADS];
    }
    __syncthreads();

    // --- Thread tile: 8 o x 8 p, p split as {4pg..4pg+3} U {64+4pg..}
    const int og = tid >> 4;          // 0..7
    const int pg = tid & 15;          // 0..15
    const int o0 = og * 8;
    const int pA = pg * 4;
    const int pB = 64 + pg * 4;

    unsigned long long A[8][4];       // [o][pair]: 0,1 = pA ; 2,3 = pB

    int cnt = 0;                      // completed-state counter (slot index)
    #pragma unroll 1
    for (int g = 0; g < NG; ++g) {
        const int s_in = c_in[g];
        if (c_start[g]) {
            #pragma unroll
            for (int i = 0; i < 8; ++i) {
                A[i][0] = 0ull; A[i][1] = 0ull; A[i][2] = 0ull; A[i][3] = 0ull;
            }
        }
        // --- GEMM: A += W[g] * state[s_in]
        {
            const float* xp = st + s_in * SLOT;
            const float* wp = wb + (g & 1) * 4096 + o0;
            #pragma unroll 8
            for (int c = 0; c < 64; ++c) {
                ulonglong2 xa = *reinterpret_cast<const ulonglong2*>(xp + pA);
                ulonglong2 xb = *reinterpret_cast<const ulonglong2*>(xp + pB);
                float4 w0 = *reinterpret_cast<const float4*>(wp);
                float4 w1 = *reinterpret_cast<const float4*>(wp + 4);
                unsigned long long s0 = splat2(w0.x), s1 = splat2(w0.y);
                unsigned long long s2 = splat2(w0.z), s3 = splat2(w0.w);
                unsigned long long s4 = splat2(w1.x), s5 = splat2(w1.y);
                unsigned long long s6 = splat2(w1.z), s7 = splat2(w1.w);
                ffma2(A[0][0], s0, xa.x); ffma2(A[0][1], s0, xa.y);
                ffma2(A[0][2], s0, xb.x); ffma2(A[0][3], s0, xb.y);
                ffma2(A[1][0], s1, xa.x); ffma2(A[1][1], s1, xa.y);
                ffma2(A[1][2], s1, xb.x); ffma2(A[1][3], s1, xb.y);
                ffma2(A[2][0], s2, xa.x); ffma2(A[2][1], s2, xa.y);
                ffma2(A[2][2], s2, xb.x); ffma2(A[2][3], s2, xb.y);
                ffma2(A[3][0], s3, xa.x); ffma2(A[3][1], s3, xa.y);
                ffma2(A[3][2], s3, xb.x); ffma2(A[3][3], s3, xb.y);
                ffma2(A[4][0], s4, xa.x); ffma2(A[4][1], s4, xa.y);
                ffma2(A[4][2], s4, xb.x); ffma2(A[4][3], s4, xb.y);
                ffma2(A[5][0], s5, xa.x); ffma2(A[5][1], s5, xa.y);
                ffma2(A[5][2], s5, xb.x); ffma2(A[5][3], s5, xb.y);
                ffma2(A[6][0], s6, xa.x); ffma2(A[6][1], s6, xa.y);
                ffma2(A[6][2], s6, xb.x); ffma2(A[6][3], s6, xb.y);
                ffma2(A[7][0], s7, xa.x); ffma2(A[7][1], s7, xa.y);
                ffma2(A[7][2], s7, xb.x); ffma2(A[7][3], s7, xb.y);
                xp += 128;
                wp += 64;
            }
        }
        // --- Completed state: relu'd -> smem slot cnt; raw -> global (nodes)
        if (c_fin[g]) {
            float* sd = st + cnt * SLOT;
            const int node = cnt - 2;
            #pragma unroll
            for (int oo = 0; oo < 8; ++oo) {
                float2 a0 = u2f2(A[oo][0]), a1 = u2f2(A[oo][1]);
                float2 b0 = u2f2(A[oo][2]), b1 = u2f2(A[oo][3]);
                if (node >= 0) {
                    float* gp = out + b * 262144 + node * 65536
                                    + (o0 + oo) * 1024 + p0;
                    *reinterpret_cast<float4*>(gp + pA) =
                        make_float4(a0.x, a0.y, a1.x, a1.y);
                    *reinterpret_cast<float4*>(gp + pB) =
                        make_float4(b0.x, b0.y, b1.x, b1.y);
                }
                *reinterpret_cast<float4*>(sd + (o0 + oo) * 128 + pA) =
                    make_float4(fmaxf(a0.x, 0.f), fmaxf(a0.y, 0.f),
                                fmaxf(a1.x, 0.f), fmaxf(a1.y, 0.f));
                *reinterpret_cast<float4*>(sd + (o0 + oo) * 128 + pB) =
                    make_float4(fmaxf(b0.x, 0.f), fmaxf(b0.y, 0.f),
                                fmaxf(b1.x, 0.f), fmaxf(b1.y, 0.f));
            }
            ++cnt;
        }
        // --- Weight staging: STS w[g+1] (in regs) to the other buffer,
        //     then prefetch LDG w[g+2] into regs
        if (g + 1 < NG) {
            float4* d = reinterpret_cast<float4*>(wb + ((g + 1) & 1) * 4096);
            #pragma unroll
            for (int j = 0; j < 8; ++j) d[tid + j * NTHREADS] = wr[j];
        }
        if (g + 2 < NG) {
            const float4* s =
                reinterpret_cast<const float4*>(g_wsp + (g + 2) * 4096);
            #pragma unroll
            for (int j = 0; j < 8; ++j) wr[j] = s[tid + j * NTHREADS];
        }
        __syncthreads();
    }
}

extern "C" void kernel_launch(void* const* d_in, const int* in_sizes, int n_in,
                              void* d_out, int out_size) {
    const float* x0    = (const float*)d_in[0];
    const float* x1    = (const float*)d_in[1];
    const float* Wpre  = (const float*)d_in[2];
    const float* Wedge = (const float*)d_in[3];
    float* out = (float*)d_out;

    prep_weights_kernel<<<256, 256>>>(Wpre, Wedge);

    cudaFuncSetAttribute(dag_kernel,
                         cudaFuncAttributeMaxDynamicSharedMemorySize,
                         SMEM_BYTES);
    dag_kernel<<<512, NTHREADS, SMEM_BYTES>>>(x0, x1, out);
}

// round 5
// speedup vs baseline: 2.1116x; 1.0196x over previous
#include <cuda_runtime.h>

// DAG fused 1x1-conv, fp32, f32x2 FMA, split-K 8x8 thread tile.
// Block = (batch, 128-position tile), 256 threads = 2 k-halves x 128.
// Each k-half computes the full 64o x 128p tile over 32 of 64 input
// channels; halves are summed at state-finish points through the
// destination state slot in smem. 6 states resident in smem (relu'd);
// raw node values go to global from kh=0 registers. Weights [g][c][o]
// double-buffered in smem, unsplatted; {w,w} pairs built with mov.b64.

#define NG        16
#define NTHREADS  256
#define SLOT      8192                       // floats per state slot (64 c x 128 p)
#define SMEM_FLOATS (6 * SLOT + 2 * 4096)    // states + 2 weight buffers
#define SMEM_BYTES  (SMEM_FLOATS * 4)        // 229376 B

// GEMM schedule: g0,g1 = preproc convs; then node i sums convs of priors.
__constant__ int c_in[NG]    = {4,5, 0,1, 0,1,2, 0,1,2,3, 0,1,2,3,4};
__constant__ int c_start[NG] = {1,1, 1,0, 1,0,0, 1,0,0,0, 1,0,0,0,0};
__constant__ int c_fin[NG]   = {1,1, 0,1, 0,0,1, 0,0,0,1, 0,0,0,0,1};

// [g][c][o] transposed weights
__device__ __align__(16) float g_wsp[NG * 4096];

__global__ void prep_weights_kernel(const float* __restrict__ Wpre,
                                    const float* __restrict__ Wedge) {
    int idx = blockIdx.x * blockDim.x + threadIdx.x;
    if (idx >= NG * 4096) return;
    int g = idx >> 12;
    int r = idx & 4095;
    int o = r >> 6;
    int c = r & 63;
    float w = (g < 2) ? Wpre[g * 4096 + o * 64 + c]
                      : Wedge[(g - 2) * 4096 + o * 64 + c];
    g_wsp[(g * 64 + c) * 64 + o] = w;
}

__device__ __forceinline__ void ffma2(unsigned long long& d,
                                      unsigned long long a,
                                      unsigned long long b) {
    asm("fma.rn.f32x2 %0, %1, %2, %0;" : "+l"(d) : "l"(a), "l"(b));
}
__device__ __forceinline__ unsigned long long splat2(float w) {
    unsigned long long r;
    asm("mov.b64 %0, {%1, %1};" : "=l"(r) : "f"(w));
    return r;
}
__device__ __forceinline__ float2 u2f2(unsigned long long v) {
    float2 r;
    asm("mov.b64 {%0, %1}, %2;" : "=f"(r.x), "=f"(r.y) : "l"(v));
    return r;
}

__global__ void __launch_bounds__(NTHREADS, 1)
dag_kernel(const float* __restrict__ x0,
           const float* __restrict__ x1,
           float* __restrict__ out) {
    extern __shared__ __align__(16) float sm[];
    float* st = sm;                 // 6 state slots [64 c][128 p]
    float* wb = sm + 6 * SLOT;      // 2 weight buffers [64 c][64 o]

    const int tid = threadIdx.x;
    const int kh  = tid >> 7;       // k-half: c in [kh*32, kh*32+32)
    const int t   = tid & 127;
    const int b   = blockIdx.x >> 3;
    const int p0  = (blockIdx.x & 7) * 128;

    // --- Stage raw x0 -> slot 4, x1 -> slot 5
    {
        const float4* gx0 = reinterpret_cast<const float4*>(x0 + b * 65536 + p0);
        const float4* gx1 = reinterpret_cast<const float4*>(x1 + b * 65536 + p0);
        float4* s4 = reinterpret_cast<float4*>(st + 4 * SLOT);
        float4* s5 = reinterpret_cast<float4*>(st + 5 * SLOT);
        #pragma unroll
        for (int j = 0; j < 8; ++j) {
            int id = tid + j * NTHREADS;     // 0..2047 float4s = [64 c][32 q]
            int c = id >> 5;
            int q = id & 31;
            s4[id] = gx0[c * 256 + q];
            s5[id] = gx1[c * 256 + q];
        }
    }

    // --- Weight prologue: w0 -> buf0 ; w1 prefetched into regs
    float4 wr[4];
    {
        const float4* s0 = reinterpret_cast<const float4*>(g_wsp);
        #pragma unroll
        for (int j = 0; j < 4; ++j) wr[j] = s0[tid + j * NTHREADS];
        float4* d0 = reinterpret_cast<float4*>(wb);
        #pragma unroll
        for (int j = 0; j < 4; ++j) d0[tid + j * NTHREADS] = wr[j];
        const float4* s1 = reinterpret_cast<const float4*>(g_wsp + 4096);
        #pragma unroll
        for (int j = 0; j < 4; ++j) wr[j] = s1[tid + j * NTHREADS];
    }
    __syncthreads();

    // --- Thread tile: 8 o x 8 p (p split {4pg..} U {64+4pg..})
    const int og = t >> 4;
    const int pg = t & 15;
    const int o0 = og * 8;
    const int pA = pg * 4;
    const int pB = 64 + pg * 4;

    unsigned long long A[8][4];       // [o][pair]: 0,1 = pA ; 2,3 = pB

    int cnt = 0;                      // completed-state counter
    #pragma unroll 1
    for (int g = 0; g < NG; ++g) {
        const int s_in = c_in[g];
        if (c_start[g]) {
            #pragma unroll
            for (int i = 0; i < 8; ++i) {
                A[i][0] = 0ull; A[i][1] = 0ull; A[i][2] = 0ull; A[i][3] = 0ull;
            }
        }
        // --- GEMM: A += W[g][c-half] * state[s_in][c-half]
        {
            const float* xp = st + s_in * SLOT + kh * 4096;        // 32 c rows
            const float* wp = wb + (g & 1) * 4096 + kh * 2048 + o0;
            #pragma unroll 8
            for (int c = 0; c < 32; ++c) {
                ulonglong2 xa = *reinterpret_cast<const ulonglong2*>(xp + pA);
                ulonglong2 xb = *reinterpret_cast<const ulonglong2*>(xp + pB);
                float4 w0 = *reinterpret_cast<const float4*>(wp);
                float4 w1 = *reinterpret_cast<const float4*>(wp + 4);
                unsigned long long s0 = splat2(w0.x), s1 = splat2(w0.y);
                unsigned long long s2 = splat2(w0.z), s3 = splat2(w0.w);
                unsigned long long s4 = splat2(w1.x), s5 = splat2(w1.y);
                unsigned long long s6 = splat2(w1.z), s7 = splat2(w1.w);
                ffma2(A[0][0], s0, xa.x); ffma2(A[0][1], s0, xa.y);
                ffma2(A[0][2], s0, xb.x); ffma2(A[0][3], s0, xb.y);
                ffma2(A[1][0], s1, xa.x); ffma2(A[1][1], s1, xa.y);
                ffma2(A[1][2], s1, xb.x); ffma2(A[1][3], s1, xb.y);
                ffma2(A[2][0], s2, xa.x); ffma2(A[2][1], s2, xa.y);
                ffma2(A[2][2], s2, xb.x); ffma2(A[2][3], s2, xb.y);
                ffma2(A[3][0], s3, xa.x); ffma2(A[3][1], s3, xa.y);
                ffma2(A[3][2], s3, xb.x); ffma2(A[3][3], s3, xb.y);
                ffma2(A[4][0], s4, xa.x); ffma2(A[4][1], s4, xa.y);
                ffma2(A[4][2], s4, xb.x); ffma2(A[4][3], s4, xb.y);
                ffma2(A[5][0], s5, xa.x); ffma2(A[5][1], s5, xa.y);
                ffma2(A[5][2], s5, xb.x); ffma2(A[5][3], s5, xb.y);
                ffma2(A[6][0], s6, xa.x); ffma2(A[6][1], s6, xa.y);
                ffma2(A[6][2], s6, xb.x); ffma2(A[6][3], s6, xb.y);
                ffma2(A[7][0], s7, xa.x); ffma2(A[7][1], s7, xa.y);
                ffma2(A[7][2], s7, xb.x); ffma2(A[7][3], s7, xb.y);
                xp += 128;
                wp += 64;
            }
        }
        // --- State finished: combine k-halves through the dest slot,
        //     raw -> global (nodes), relu'd -> smem slot cnt
        if (c_fin[g]) {
            float* sd = st + cnt * SLOT;
            const int node = cnt - 2;
            __syncthreads();                  // all reads of old slot done
            if (kh) {                         // upper half: dump raw partials
                #pragma unroll
                for (int oo = 0; oo < 8; ++oo) {
                    float2 a0 = u2f2(A[oo][0]), a1 = u2f2(A[oo][1]);
                    float2 b0 = u2f2(A[oo][2]), b1 = u2f2(A[oo][3]);
                    *reinterpret_cast<float4*>(sd + (o0 + oo) * 128 + pA) =
                        make_float4(a0.x, a0.y, a1.x, a1.y);
                    *reinterpret_cast<float4*>(sd + (o0 + oo) * 128 + pB) =
                        make_float4(b0.x, b0.y, b1.x, b1.y);
                }
            }
            __syncthreads();
            if (!kh) {                        // lower half: reduce + emit
                #pragma unroll
                for (int oo = 0; oo < 8; ++oo) {
                    float4 u = *reinterpret_cast<const float4*>(
                                   sd + (o0 + oo) * 128 + pA);
                    float4 v = *reinterpret_cast<const float4*>(
                                   sd + (o0 + oo) * 128 + pB);
                    float2 a0 = u2f2(A[oo][0]), a1 = u2f2(A[oo][1]);
                    float2 b0 = u2f2(A[oo][2]), b1 = u2f2(A[oo][3]);
                    float4 ra = make_float4(a0.x + u.x, a0.y + u.y,
                                            a1.x + u.z, a1.y + u.w);
                    float4 rb = make_float4(b0.x + v.x, b0.y + v.y,
                                            b1.x + v.z, b1.y + v.w);
                    if (node >= 0) {
                        float* gp = out + b * 262144 + node * 65536
                                        + (o0 + oo) * 1024 + p0;
                        *reinterpret_cast<float4*>(gp + pA) = ra;
                        *reinterpret_cast<float4*>(gp + pB) = rb;
                    }
                    *reinterpret_cast<float4*>(sd + (o0 + oo) * 128 + pA) =
                        make_float4(fmaxf(ra.x, 0.f), fmaxf(ra.y, 0.f),
                                    fmaxf(ra.z, 0.f), fmaxf(ra.w, 0.f));
                    *reinterpret_cast<float4*>(sd + (o0 + oo) * 128 + pB) =
                        make_float4(fmaxf(rb.x, 0.f), fmaxf(rb.y, 0.f),
                                    fmaxf(rb.z, 0.f), fmaxf(rb.w, 0.f));
                }
            }
            ++cnt;
        }
        // --- Weight staging: STS w[g+1] (in regs), prefetch LDG w[g+2]
        if (g + 1 < NG) {
            float4* d = reinterpret_cast<float4*>(wb + ((g + 1) & 1) * 4096);
            #pragma unroll
            for (int j = 0; j < 4; ++j) d[tid + j * NTHREADS] = wr[j];
        }
        if (g + 2 < NG) {
            const float4* s =
                reinterpret_cast<const float4*>(g_wsp + (g + 2) * 4096);
            #pragma unroll
            for (int j = 0; j < 4; ++j) wr[j] = s[tid + j * NTHREADS];
        }
        __syncthreads();
    }
}

extern "C" void kernel_launch(void* const* d_in, const int* in_sizes, int n_in,
                              void* d_out, int out_size) {
    const float* x0    = (const float*)d_in[0];
    const float* x1    = (const float*)d_in[1];
    const float* Wpre  = (const float*)d_in[2];
    const float* Wedge = (const float*)d_in[3];
    float* out = (float*)d_out;

    prep_weights_kernel<<<256, 256>>>(Wpre, Wedge);

    cudaFuncSetAttribute(dag_kernel,
                         cudaFuncAttributeMaxDynamicSharedMemorySize,
                         SMEM_BYTES);
    dag_kernel<<<512, NTHREADS, SMEM_BYTES>>>(x0, x1, out);
}

// round 6
// speedup vs baseline: 2.3246x; 1.1009x over previous
#include <cuda_runtime.h>

// DAG fused 1x1-conv, fp32, f32x2 FMA. 64-pos tiles, 2 blocks/SM.
// Block = (batch, 64-position tile), 128 threads, thread tile 8o x 4p.
// 5 state slots in smem (s0,s1,n0,n1,n2; relu'd) — node3 never consumed,
// goes straight to global. x0/x1 staged into the n1/n2 slots (free until
// their fin points). Weights [g][c][o] double-buffered in smem, unsplatted;
// {w,w} pairs via mov.b64. FMA order grouped by x operand for .reuse.

#define NG        16
#define NTHREADS  128
#define TPOS      64
#define SLOT      4096                       // floats per slot (64 c x 64 p)
#define SMEM_FLOATS (5 * SLOT + 2 * 4096)    // 5 states + 2 weight buffers
#define SMEM_BYTES  (SMEM_FLOATS * 4)        // 114688 B = 112 KB

// Schedule. Slots: 0=s0 1=s1 2=n0 3=n1 4=n2. x0 staged in slot3, x1 in
// slot4 (consumed at g0/g1, overwritten at fins g6/g10).
// c_fins: -1 none; 0..4 relu->slot (2..4 also raw->global node slot-2);
//          5 = node3, raw->global only.
__constant__ int c_in[NG]    = {3,4, 0,1, 0,1,2, 0,1,2,3, 0,1,2,3,4};
__constant__ int c_start[NG] = {1,1, 1,0, 1,0,0, 1,0,0,0, 1,0,0,0,0};
__constant__ int c_fins[NG]  = {0,1, -1,2, -1,-1,3, -1,-1,-1,4, -1,-1,-1,-1,5};

// [g][c][o] transposed weights
__device__ __align__(16) float g_wsp[NG * 4096];

__global__ void prep_weights_kernel(const float* __restrict__ Wpre,
                                    const float* __restrict__ Wedge) {
    int idx = blockIdx.x * blockDim.x + threadIdx.x;
    if (idx >= NG * 4096) return;
    int g = idx >> 12;
    int r = idx & 4095;
    int o = r >> 6;
    int c = r & 63;
    float w = (g < 2) ? Wpre[g * 4096 + o * 64 + c]
                      : Wedge[(g - 2) * 4096 + o * 64 + c];
    g_wsp[(g * 64 + c) * 64 + o] = w;
}

__device__ __forceinline__ void ffma2(unsigned long long& d,
                                      unsigned long long a,
                                      unsigned long long b) {
    asm("fma.rn.f32x2 %0, %1, %2, %0;" : "+l"(d) : "l"(a), "l"(b));
}
__device__ __forceinline__ unsigned long long splat2(float w) {
    unsigned long long r;
    asm("mov.b64 %0, {%1, %1};" : "=l"(r) : "f"(w));
    return r;
}
__device__ __forceinline__ float2 u2f2(unsigned long long v) {
    float2 r;
    asm("mov.b64 {%0, %1}, %2;" : "=f"(r.x), "=f"(r.y) : "l"(v));
    return r;
}

__global__ void __launch_bounds__(NTHREADS, 2)
dag_kernel(const float* __restrict__ x0,
           const float* __restrict__ x1,
           float* __restrict__ out) {
    extern __shared__ __align__(16) float sm[];
    float* st = sm;                 // 5 state slots [64 c][64 p]
    float* wb = sm + 5 * SLOT;      // 2 weight buffers [64 c][64 o]

    const int tid = threadIdx.x;
    const int b   = blockIdx.x >> 4;
    const int p0  = (blockIdx.x & 15) * TPOS;

    // --- Stage raw x0 -> slot3, x1 -> slot4
    {
        const float4* gx0 = reinterpret_cast<const float4*>(x0 + b * 65536 + p0);
        const float4* gx1 = reinterpret_cast<const float4*>(x1 + b * 65536 + p0);
        float4* s3 = reinterpret_cast<float4*>(st + 3 * SLOT);
        float4* s4 = reinterpret_cast<float4*>(st + 4 * SLOT);
        #pragma unroll
        for (int j = 0; j < 8; ++j) {
            int id = tid + j * NTHREADS;     // 0..1023 float4s = [64 c][16 q]
            int c = id >> 4;
            int q = id & 15;
            s3[id] = gx0[c * 256 + q];
            s4[id] = gx1[c * 256 + q];
        }
    }

    // --- Weight prologue: w0 -> buf0 ; w1 prefetched into regs
    float4 wr[8];
    {
        const float4* s0 = reinterpret_cast<const float4*>(g_wsp);
        #pragma unroll
        for (int j = 0; j < 8; ++j) wr[j] = s0[tid + j * NTHREADS];
        float4* d0 = reinterpret_cast<float4*>(wb);
        #pragma unroll
        for (int j = 0; j < 8; ++j) d0[tid + j * NTHREADS] = wr[j];
        const float4* s1 = reinterpret_cast<const float4*>(g_wsp + 4096);
        #pragma unroll
        for (int j = 0; j < 8; ++j) wr[j] = s1[tid + j * NTHREADS];
    }
    __syncthreads();

    // --- Thread tile: 8 o x 4 p
    const int og = tid >> 4;          // 0..7
    const int pg = tid & 15;          // 0..15
    const int o0 = og * 8;
    const int pA = pg * 4;

    unsigned long long A[8][2];       // [o][pos-pair]

    #pragma unroll 1
    for (int g = 0; g < NG; ++g) {
        const int s_in = c_in[g];
        if (c_start[g]) {
            #pragma unroll
            for (int i = 0; i < 8; ++i) { A[i][0] = 0ull; A[i][1] = 0ull; }
        }
        // --- GEMM: A += W[g] * state[s_in]
        {
            const float* xp = st + s_in * SLOT + pA;
            const float* wp = wb + (g & 1) * 4096 + o0;
            #pragma unroll 8
            for (int c = 0; c < 64; ++c) {
                ulonglong2 xa = *reinterpret_cast<const ulonglong2*>(xp);
                float4 w0 = *reinterpret_cast<const float4*>(wp);
                float4 w1 = *reinterpret_cast<const float4*>(wp + 4);
                unsigned long long s0 = splat2(w0.x), s1 = splat2(w0.y);
                unsigned long long s2 = splat2(w0.z), s3 = splat2(w0.w);
                unsigned long long s4 = splat2(w1.x), s5 = splat2(w1.y);
                unsigned long long s6 = splat2(w1.z), s7 = splat2(w1.w);
                // grouped by x operand (slot-b reuse across consecutive FMAs)
                ffma2(A[0][0], s0, xa.x); ffma2(A[1][0], s1, xa.x);
                ffma2(A[2][0], s2, xa.x); ffma2(A[3][0], s3, xa.x);
                ffma2(A[4][0], s4, xa.x); ffma2(A[5][0], s5, xa.x);
                ffma2(A[6][0], s6, xa.x); ffma2(A[7][0], s7, xa.x);
                ffma2(A[0][1], s0, xa.y); ffma2(A[1][1], s1, xa.y);
                ffma2(A[2][1], s2, xa.y); ffma2(A[3][1], s3, xa.y);
                ffma2(A[4][1], s4, xa.y); ffma2(A[5][1], s5, xa.y);
                ffma2(A[6][1], s6, xa.y); ffma2(A[7][1], s7, xa.y);
                xp += TPOS;
                wp += 64;
            }
        }
        // --- State finished
        {
            const int f = c_fins[g];
            if (f >= 0) {
                if (f >= 2) {   // node raw -> global
                    const int node = (f == 5) ? 3 : (f - 2);
                    float* gp = out + b * 262144 + node * 65536 + p0 + pA;
                    #pragma unroll
                    for (int oo = 0; oo < 8; ++oo) {
                        float2 a0 = u2f2(A[oo][0]), a1 = u2f2(A[oo][1]);
                        *reinterpret_cast<float4*>(gp + (o0 + oo) * 1024) =
                            make_float4(a0.x, a0.y, a1.x, a1.y);
                    }
                }
                if (f <= 4) {   // relu'd -> smem slot f
                    float* sd = st + f * SLOT + pA;
                    #pragma unroll
                    for (int oo = 0; oo < 8; ++oo) {
                        float2 a0 = u2f2(A[oo][0]), a1 = u2f2(A[oo][1]);
                        *reinterpret_cast<float4*>(sd + (o0 + oo) * TPOS) =
                            make_float4(fmaxf(a0.x, 0.f), fmaxf(a0.y, 0.f),
                                        fmaxf(a1.x, 0.f), fmaxf(a1.y, 0.f));
                    }
                }
            }
        }
        // --- Weight staging: STS w[g+1] (in regs), prefetch LDG w[g+2]
        if (g + 1 < NG) {
            float4* d = reinterpret_cast<float4*>(wb + ((g + 1) & 1) * 4096);
            #pragma unroll
            for (int j = 0; j < 8; ++j) d[tid + j * NTHREADS] = wr[j];
        }
        if (g + 2 < NG) {
            const float4* s =
                reinterpret_cast<const float4*>(g_wsp + (g + 2) * 4096);
            #pragma unroll
            for (int j = 0; j < 8; ++j) wr[j] = s[tid + j * NTHREADS];
        }
        __syncthreads();
    }
}

extern "C" void kernel_launch(void* const* d_in, const int* in_sizes, int n_in,
                              void* d_out, int out_size) {
    const float* x0    = (const float*)d_in[0];
    const float* x1    = (const float*)d_in[1];
    const float* Wpre  = (const float*)d_in[2];
    const float* Wedge = (const float*)d_in[3];
    float* out = (float*)d_out;

    prep_weights_kernel<<<256, 256>>>(Wpre, Wedge);

    cudaFuncSetAttribute(dag_kernel,
                         cudaFuncAttributeMaxDynamicSharedMemorySize,
                         SMEM_BYTES);
    dag_kernel<<<1024, NTHREADS, SMEM_BYTES>>>(x0, x1, out);
}